// round 4
// baseline (speedup 1.0000x reference)
#include <cuda_runtime.h>
#include <cuda_bf16.h>
#include <cstdint>

#define NB 8192
#define DD 256
#define BM 128
#define BN 128
#define BK 64
#define LDS_ST 72                       // padded bf16 row stride (conflict-free ldmatrix)
#define STAGE_ELEMS (BM * LDS_ST)       // 9216 bf16
#define STAGE_BYTES (STAGE_ELEMS * 2)   // 18432 B
#define SMEM_BYTES (4 * STAGE_BYTES + 256 * 4 + BM * 6 * 4)  // 77824 B

#define INV_T 14.285714285714286f
#define THR_POS 0.5f
#define THR_NEG 0.3f
#define NEG_W 0.3f

__device__ __nv_bfloat16 g_nrm[NB * DD];   // normalized features, bf16
__device__ float g_rowstats[6 * NB];       // [denom, S1, W1, pos_cnt, S2, neg_cnt] x NB

// ---------------------------------------------------------------- helpers
__device__ __forceinline__ void cp_async16(void* dst, const void* src) {
    unsigned s = (unsigned)__cvta_generic_to_shared(dst);
    asm volatile("cp.async.cg.shared.global [%0], [%1], 16;\n" :: "r"(s), "l"(src));
}

__device__ __forceinline__ void ldsm4(uint32_t& r0, uint32_t& r1, uint32_t& r2, uint32_t& r3,
                                      unsigned addr) {
    asm volatile("ldmatrix.sync.aligned.m8n8.x4.shared.b16 {%0,%1,%2,%3}, [%4];\n"
                 : "=r"(r0), "=r"(r1), "=r"(r2), "=r"(r3) : "r"(addr));
}

__device__ __forceinline__ void mma16816(float* d, const uint32_t* a, const uint32_t* b) {
    asm volatile(
        "mma.sync.aligned.m16n8k16.row.col.f32.bf16.bf16.f32 "
        "{%0,%1,%2,%3}, {%4,%5,%6,%7}, {%8,%9}, {%0,%1,%2,%3};\n"
        : "+f"(d[0]), "+f"(d[1]), "+f"(d[2]), "+f"(d[3])
        : "r"(a[0]), "r"(a[1]), "r"(a[2]), "r"(a[3]), "r"(b[0]), "r"(b[1]));
}

__device__ __forceinline__ void prefetch_tiles(const __nv_bfloat16* gA, const __nv_bfloat16* gB,
                                               __nv_bfloat16* sA, __nv_bfloat16* sB, int t) {
    // 128 rows x 64 cols bf16 per matrix = 1024 x 16B chunks, 256 threads -> 4 each
#pragma unroll
    for (int it = 0; it < 4; ++it) {
        int c = t + it * 256;
        int r = c >> 3, cc = c & 7;
        cp_async16(sA + r * LDS_ST + cc * 8, gA + (size_t)r * DD + cc * 8);
        cp_async16(sB + r * LDS_ST + cc * 8, gB + (size_t)r * DD + cc * 8);
    }
}

__device__ __forceinline__ void contrib(float s, int gi, int li, int gj, int lj, float* v) {
    if (gj == gi) return;                       // exclude self
    float l = (s - 1.0f) * INV_T;               // stabilized logit (shift cancels exactly)
    float e = __expf(l);
    v[0] += e;                                  // denom
    if (li == lj) {
        float w = (s < THR_POS) ? (1.5f - s) : 1.0f;   // 1+(0.5-s)/0.5*0.5
        v[1] += w * l;                          // S1
        v[2] += w;                              // W1
        v[3] += 1.0f;                           // pos_cnt
    } else {
        float w = (s > THR_NEG) ? fmaf(s - THR_NEG, 1.4285714285714286f, 1.0f) : 1.0f;
        v[4] += w * e;                          // S2
        v[5] += 1.0f;                           // neg_cnt
    }
}

// ------------------------------------------------- kernel 1: normalize + zero stats
__global__ void norm_zero_kernel(const float* __restrict__ feat) {
    int gt = blockIdx.x * 256 + threadIdx.x;
    if (gt < 6 * NB) g_rowstats[gt] = 0.0f;

    int warp = threadIdx.x >> 5;
    int lane = threadIdx.x & 31;
    int row = blockIdx.x * 8 + warp;

    const float4* src = reinterpret_cast<const float4*>(feat) + (size_t)row * (DD / 4) + lane * 2;
    float4 a = src[0];
    float4 b = src[1];
    float ss = a.x * a.x + a.y * a.y + a.z * a.z + a.w * a.w
             + b.x * b.x + b.y * b.y + b.z * b.z + b.w * b.w;
#pragma unroll
    for (int o = 16; o > 0; o >>= 1) ss += __shfl_xor_sync(0xffffffffu, ss, o);
    float inv = rsqrtf(ss);

    union { __nv_bfloat162 h[4]; uint4 u; } pk;
    pk.h[0] = __floats2bfloat162_rn(a.x * inv, a.y * inv);
    pk.h[1] = __floats2bfloat162_rn(a.z * inv, a.w * inv);
    pk.h[2] = __floats2bfloat162_rn(b.x * inv, b.y * inv);
    pk.h[3] = __floats2bfloat162_rn(b.z * inv, b.w * inv);
    reinterpret_cast<uint4*>(g_nrm)[(size_t)row * (DD / 8) + lane] = pk.u;
}

// ------------------------------------------------- kernel 2: fused GEMM + W2ML epilogue
__global__ __launch_bounds__(256, 2)
void w2ml_main_kernel(const int* __restrict__ labels) {
    extern __shared__ char smem[];
    __nv_bfloat16* As = reinterpret_cast<__nv_bfloat16*>(smem);      // [2][128][72]
    __nv_bfloat16* Bs = As + 2 * STAGE_ELEMS;                        // [2][128][72]
    int* sLab = reinterpret_cast<int*>(Bs + 2 * STAGE_ELEMS);        // [256]
    float* rowAcc = reinterpret_cast<float*>(sLab + 256);            // [128][6]

    const int t = threadIdx.x;
    const int i0 = blockIdx.y * BM;
    const int j0 = blockIdx.x * BN;

    if (t < 128) sLab[t] = labels[i0 + t];
    else         sLab[t] = labels[j0 + t - 128];
    for (int k = t; k < BM * 6; k += 256) rowAcc[k] = 0.0f;

    const int lane = t & 31;
    const int warpId = t >> 5;
    const int wm = warpId >> 2;     // 0..1 (m)
    const int wn = warpId & 3;      // 0..3 (n)

    unsigned aAddr[4], bAddr[2];
    {
        int coff = (lane >> 4) * 8;  // halves
#pragma unroll
        for (int mi = 0; mi < 4; ++mi) {
            int r = wm * 64 + mi * 16 + (lane & 15);
            aAddr[mi] = (unsigned)__cvta_generic_to_shared(As + r * LDS_ST + coff);
        }
        int bcoff = ((lane >> 3) & 1) * 8;
#pragma unroll
        for (int np = 0; np < 2; ++np) {
            int r = wn * 32 + np * 16 + (lane & 7) + ((lane >> 4) << 3);
            bAddr[np] = (unsigned)__cvta_generic_to_shared(Bs + r * LDS_ST + bcoff);
        }
    }

    float acc[4][4][4];
#pragma unroll
    for (int mi = 0; mi < 4; ++mi)
#pragma unroll
        for (int ni = 0; ni < 4; ++ni)
#pragma unroll
            for (int r = 0; r < 4; ++r) acc[mi][ni][r] = 0.0f;

    const __nv_bfloat16* gA = g_nrm + (size_t)i0 * DD;
    const __nv_bfloat16* gB = g_nrm + (size_t)j0 * DD;

    prefetch_tiles(gA, gB, As, Bs, t);
    asm volatile("cp.async.commit_group;\n" ::: "memory");

#pragma unroll
    for (int kb = 0; kb < 4; ++kb) {
        if (kb < 3) {
            int st = (kb + 1) & 1;
            prefetch_tiles(gA + (kb + 1) * BK, gB + (kb + 1) * BK,
                           As + st * STAGE_ELEMS, Bs + st * STAGE_ELEMS, t);
            asm volatile("cp.async.commit_group;\n" ::: "memory");
            asm volatile("cp.async.wait_group 1;\n" ::: "memory");
        } else {
            asm volatile("cp.async.wait_group 0;\n" ::: "memory");
        }
        __syncthreads();

        unsigned soff = (kb & 1) * STAGE_BYTES;
#pragma unroll
        for (int ks = 0; ks < 4; ++ks) {
            unsigned off = soff + ks * 32;   // k16 step = 32 bytes
            uint32_t bf[4][2];
#pragma unroll
            for (int np = 0; np < 2; ++np) {
                uint32_t r0, r1, r2, r3;
                ldsm4(r0, r1, r2, r3, bAddr[np] + off);
                bf[np * 2][0] = r0;     bf[np * 2][1] = r1;
                bf[np * 2 + 1][0] = r2; bf[np * 2 + 1][1] = r3;
            }
#pragma unroll
            for (int mi = 0; mi < 4; ++mi) {
                uint32_t a[4];
                ldsm4(a[0], a[1], a[2], a[3], aAddr[mi] + off);
#pragma unroll
                for (int ni = 0; ni < 4; ++ni) mma16816(acc[mi][ni], a, bf[ni]);
            }
        }
        __syncthreads();
    }

    // ---- epilogue: per-element W2ML terms, reduce to per-row stats ----
    const int qrow = lane >> 2;
    const int qc = (lane & 3) << 1;
#pragma unroll
    for (int mi = 0; mi < 4; ++mi) {
        int r0 = wm * 64 + mi * 16 + qrow;
        int r1 = r0 + 8;
        int gi0 = i0 + r0, gi1 = i0 + r1;
        int lb0 = sLab[r0], lb1 = sLab[r1];
        float v0[6] = {0, 0, 0, 0, 0, 0};
        float v1[6] = {0, 0, 0, 0, 0, 0};
#pragma unroll
        for (int ni = 0; ni < 4; ++ni) {
            int cbase = wn * 32 + ni * 8 + qc;
#pragma unroll
            for (int e = 0; e < 2; ++e) {
                int c = cbase + e;
                int gj = j0 + c;
                int lbj = sLab[128 + c];
                contrib(acc[mi][ni][e],     gi0, lb0, gj, lbj, v0);
                contrib(acc[mi][ni][2 + e], gi1, lb1, gj, lbj, v1);
            }
        }
#pragma unroll
        for (int k = 0; k < 6; ++k) {
            v0[k] += __shfl_xor_sync(0xffffffffu, v0[k], 1);
            v0[k] += __shfl_xor_sync(0xffffffffu, v0[k], 2);
            v1[k] += __shfl_xor_sync(0xffffffffu, v1[k], 1);
            v1[k] += __shfl_xor_sync(0xffffffffu, v1[k], 2);
        }
        if ((lane & 3) == 0) {
#pragma unroll
            for (int k = 0; k < 6; ++k) {
                atomicAdd(&rowAcc[r0 * 6 + k], v0[k]);
                atomicAdd(&rowAcc[r1 * 6 + k], v1[k]);
            }
        }
    }
    __syncthreads();

    if (t < 128) {
        int gr = i0 + t;
#pragma unroll
        for (int k = 0; k < 6; ++k)
            atomicAdd(&g_rowstats[k * NB + gr], rowAcc[t * 6 + k]);
    }
}

// ------------------------------------------------- kernel 3: finalize to scalar
__global__ void finalize_kernel(float* __restrict__ out) {
    __shared__ float sp[256], sn[256];
    int t = threadIdx.x;
    float ps = 0.0f, ns = 0.0f;
    for (int r = t; r < NB; r += 256) {
        float denom = g_rowstats[r];
        float S1 = g_rowstats[NB + r];
        float W1 = g_rowstats[2 * NB + r];
        float pc = g_rowstats[3 * NB + r];
        float S2 = g_rowstats[4 * NB + r];
        float nc = g_rowstats[5 * NB + r];
        float logd = __logf(denom);
        ps -= (S1 - W1 * logd) / fmaxf(pc, 1.0f);
        ns += (S2 / denom) / fmaxf(nc, 1.0f);
    }
    sp[t] = ps; sn[t] = ns;
    __syncthreads();
#pragma unroll
    for (int s = 128; s > 0; s >>= 1) {
        if (t < s) { sp[t] += sp[t + s]; sn[t] += sn[t + s]; }
        __syncthreads();
    }
    if (t == 0) out[0] = sp[0] * (1.0f / NB) + NEG_W * (sn[0] * (1.0f / NB));
}

// ------------------------------------------------- launch
extern "C" void kernel_launch(void* const* d_in, const int* in_sizes, int n_in,
                              void* d_out, int out_size) {
    const float* feat;
    const int* labels;
    if (in_sizes[0] == NB * DD) {
        feat = (const float*)d_in[0];
        labels = (const int*)d_in[1];
    } else {
        feat = (const float*)d_in[1];
        labels = (const int*)d_in[0];
    }

    cudaFuncSetAttribute(w2ml_main_kernel,
                         cudaFuncAttributeMaxDynamicSharedMemorySize, SMEM_BYTES);

    norm_zero_kernel<<<NB / 8, 256>>>(feat);

    dim3 grid(NB / BN, NB / BM);
    w2ml_main_kernel<<<grid, 256, SMEM_BYTES>>>(labels);

    finalize_kernel<<<1, 256>>>((float*)d_out);
}

// round 5
// speedup vs baseline: 1.4773x; 1.4773x over previous
#include <cuda_runtime.h>
#include <cuda_bf16.h>
#include <cstdint>

#define NB 8192
#define DD 256
#define BM 128
#define BN 128
#define BK 64
#define NT 64                           // tiles per dimension (NB/BM)
#define NTILES (NT * (NT + 1) / 2)      // 2080 upper-triangular tiles
#define LDS_ST 72                       // padded bf16 row stride (conflict-free ldmatrix)
#define STAGE_ELEMS (BM * LDS_ST)       // 9216 bf16
#define STAGE_BYTES (STAGE_ELEMS * 2)   // 18432 B
// 4 stages + 256 labels + rowAcc[128][4] + colAcc[128][4]
#define SMEM_BYTES (4 * STAGE_BYTES + 256 * 4 + 2 * BM * 4 * 4)  // 78848 B

#define INV_T 14.285714285714286f
#define NEG_W 0.3f

__device__ __nv_bfloat16 g_nrm[NB * DD];   // normalized features, bf16
__device__ float g_rowstats[4 * NB];       // [denom, S1, W1, S2] x NB

// ---------------------------------------------------------------- helpers
__device__ __forceinline__ void cp_async16(void* dst, const void* src) {
    unsigned s = (unsigned)__cvta_generic_to_shared(dst);
    asm volatile("cp.async.cg.shared.global [%0], [%1], 16;\n" :: "r"(s), "l"(src));
}

__device__ __forceinline__ void ldsm4(uint32_t& r0, uint32_t& r1, uint32_t& r2, uint32_t& r3,
                                      unsigned addr) {
    asm volatile("ldmatrix.sync.aligned.m8n8.x4.shared.b16 {%0,%1,%2,%3}, [%4];\n"
                 : "=r"(r0), "=r"(r1), "=r"(r2), "=r"(r3) : "r"(addr));
}

__device__ __forceinline__ void mma16816(float* d, const uint32_t* a, const uint32_t* b) {
    asm volatile(
        "mma.sync.aligned.m16n8k16.row.col.f32.bf16.bf16.f32 "
        "{%0,%1,%2,%3}, {%4,%5,%6,%7}, {%8,%9}, {%0,%1,%2,%3};\n"
        : "+f"(d[0]), "+f"(d[1]), "+f"(d[2]), "+f"(d[3])
        : "r"(a[0]), "r"(a[1]), "r"(a[2]), "r"(a[3]), "r"(b[0]), "r"(b[1]));
}

__device__ __forceinline__ void prefetch_tiles(const __nv_bfloat16* gA, const __nv_bfloat16* gB,
                                               __nv_bfloat16* sA, __nv_bfloat16* sB, int t) {
#pragma unroll
    for (int it = 0; it < 4; ++it) {
        int c = t + it * 256;
        int r = c >> 3, cc = c & 7;
        cp_async16(sA + r * LDS_ST + cc * 8, gA + (size_t)r * DD + cc * 8);
        cp_async16(sB + r * LDS_ST + cc * 8, gB + (size_t)r * DD + cc * 8);
    }
}

// one symmetric contribution: adds 4-stat vector to a row acc and a col acc
__device__ __forceinline__ void contrib2(float s, bool self, bool same,
                                         float* vr, float* vc) {
    if (self) return;
    float l = (s - 1.0f) * INV_T;
    float e = __expf(l);
    float a1, a2, a3;
    if (same) {
        float w = (s < 0.5f) ? (1.5f - s) : 1.0f;   // 1+(0.5-s)/0.5*0.5 (continuous)
        a1 = w * l; a2 = w; a3 = 0.0f;
    } else {
        float w = (s > 0.3f) ? fmaf(s - 0.3f, 1.4285714285714286f, 1.0f) : 1.0f;
        a1 = 0.0f; a2 = 0.0f; a3 = w * e;
    }
    vr[0] += e;  vr[1] += a1; vr[2] += a2; vr[3] += a3;
    vc[0] += e;  vc[1] += a1; vc[2] += a2; vc[3] += a3;
}

// ------------------------------------------------- kernel 1: normalize + zero stats
__global__ void norm_zero_kernel(const float* __restrict__ feat) {
    int gt = blockIdx.x * 256 + threadIdx.x;
    if (gt < 4 * NB) g_rowstats[gt] = 0.0f;

    int warp = threadIdx.x >> 5;
    int lane = threadIdx.x & 31;
    int row = blockIdx.x * 8 + warp;

    const float4* src = reinterpret_cast<const float4*>(feat) + (size_t)row * (DD / 4) + lane * 2;
    float4 a = src[0];
    float4 b = src[1];
    float ss = a.x * a.x + a.y * a.y + a.z * a.z + a.w * a.w
             + b.x * b.x + b.y * b.y + b.z * b.z + b.w * b.w;
#pragma unroll
    for (int o = 16; o > 0; o >>= 1) ss += __shfl_xor_sync(0xffffffffu, ss, o);
    float inv = rsqrtf(ss);

    union { __nv_bfloat162 h[4]; uint4 u; } pk;
    pk.h[0] = __floats2bfloat162_rn(a.x * inv, a.y * inv);
    pk.h[1] = __floats2bfloat162_rn(a.z * inv, a.w * inv);
    pk.h[2] = __floats2bfloat162_rn(b.x * inv, b.y * inv);
    pk.h[3] = __floats2bfloat162_rn(b.z * inv, b.w * inv);
    reinterpret_cast<uint4*>(g_nrm)[(size_t)row * (DD / 8) + lane] = pk.u;
}

// ------------------------------------------------- kernel 2: fused GEMM + W2ML epilogue
// One CTA per upper-triangular tile (bi <= bj). Off-diagonal tiles produce row
// stats for BOTH the row block (reduce over j) and the column block (reduce
// over i) from one GEMM, exploiting sim symmetry.
__global__ __launch_bounds__(256, 2)
void w2ml_main_kernel(const int* __restrict__ labels) {
    extern __shared__ char smem[];
    __nv_bfloat16* As = reinterpret_cast<__nv_bfloat16*>(smem);      // [2][128][72]
    __nv_bfloat16* Bs = As + 2 * STAGE_ELEMS;                        // [2][128][72]
    int* sLab = reinterpret_cast<int*>(Bs + 2 * STAGE_ELEMS);        // [256]
    float* rowAcc = reinterpret_cast<float*>(sLab + 256);            // [128][4]
    float* colAcc = rowAcc + BM * 4;                                 // [128][4]

    const int t = threadIdx.x;

    // decode linear tile id -> (bi, bj), bi <= bj
    int id = blockIdx.x;
    int bi = (int)((2.0f * NT + 1.0f -
                    sqrtf((2.0f * NT + 1.0f) * (2.0f * NT + 1.0f) - 8.0f * (float)id)) * 0.5f);
    // fixups (start(b) = b*(2*NT - b + 1)/2)
    while ((bi + 1) * (2 * NT - bi) / 2 <= id) ++bi;
    while (bi * (2 * NT - bi + 1) / 2 > id) --bi;
    const int bj = bi + (id - bi * (2 * NT - bi + 1) / 2);
    const bool diag = (bi == bj);

    const int i0 = bi * BM;
    const int j0 = bj * BN;

    if (t < 128) sLab[t] = labels[i0 + t];
    else         sLab[t] = labels[j0 + t - 128];
    for (int k = t; k < 2 * BM * 4; k += 256) rowAcc[k] = 0.0f;

    const int lane = t & 31;
    const int warpId = t >> 5;
    const int wm = warpId >> 2;     // 0..1 (m)
    const int wn = warpId & 3;      // 0..3 (n)

    unsigned aAddr[4], bAddr[2];
    {
        int coff = (lane >> 4) * 8;
#pragma unroll
        for (int mi = 0; mi < 4; ++mi) {
            int r = wm * 64 + mi * 16 + (lane & 15);
            aAddr[mi] = (unsigned)__cvta_generic_to_shared(As + r * LDS_ST + coff);
        }
        int bcoff = ((lane >> 3) & 1) * 8;
#pragma unroll
        for (int np = 0; np < 2; ++np) {
            int r = wn * 32 + np * 16 + (lane & 7) + ((lane >> 4) << 3);
            bAddr[np] = (unsigned)__cvta_generic_to_shared(Bs + r * LDS_ST + bcoff);
        }
    }

    float acc[4][4][4];
#pragma unroll
    for (int mi = 0; mi < 4; ++mi)
#pragma unroll
        for (int ni = 0; ni < 4; ++ni)
#pragma unroll
            for (int r = 0; r < 4; ++r) acc[mi][ni][r] = 0.0f;

    const __nv_bfloat16* gA = g_nrm + (size_t)i0 * DD;
    const __nv_bfloat16* gB = g_nrm + (size_t)j0 * DD;

    prefetch_tiles(gA, gB, As, Bs, t);
    asm volatile("cp.async.commit_group;\n" ::: "memory");

#pragma unroll
    for (int kb = 0; kb < 4; ++kb) {
        if (kb < 3) {
            int st = (kb + 1) & 1;
            prefetch_tiles(gA + (kb + 1) * BK, gB + (kb + 1) * BK,
                           As + st * STAGE_ELEMS, Bs + st * STAGE_ELEMS, t);
            asm volatile("cp.async.commit_group;\n" ::: "memory");
            asm volatile("cp.async.wait_group 1;\n" ::: "memory");
        } else {
            asm volatile("cp.async.wait_group 0;\n" ::: "memory");
        }
        __syncthreads();

        unsigned soff = (kb & 1) * STAGE_BYTES;
#pragma unroll
        for (int ks = 0; ks < 4; ++ks) {
            unsigned off = soff + ks * 32;
            uint32_t bf[4][2];
#pragma unroll
            for (int np = 0; np < 2; ++np) {
                uint32_t r0, r1, r2, r3;
                ldsm4(r0, r1, r2, r3, bAddr[np] + off);
                bf[np * 2][0] = r0;     bf[np * 2][1] = r1;
                bf[np * 2 + 1][0] = r2; bf[np * 2 + 1][1] = r3;
            }
#pragma unroll
            for (int mi = 0; mi < 4; ++mi) {
                uint32_t a[4];
                ldsm4(a[0], a[1], a[2], a[3], aAddr[mi] + off);
#pragma unroll
                for (int ni = 0; ni < 4; ++ni) mma16816(acc[mi][ni], a, bf[ni]);
            }
        }
        __syncthreads();
    }

    // ---- epilogue: symmetric W2ML terms -> row stats + column(=transposed row) stats
    const int qrow = lane >> 2;
    const int qc = (lane & 3) << 1;

    int lb0a[4], lb1a[4], rl0[4];
#pragma unroll
    for (int mi = 0; mi < 4; ++mi) {
        int r0 = wm * 64 + mi * 16 + qrow;
        rl0[mi] = r0;
        lb0a[mi] = sLab[r0];
        lb1a[mi] = sLab[r0 + 8];
    }

    float vr[4][2][4];
#pragma unroll
    for (int mi = 0; mi < 4; ++mi)
#pragma unroll
        for (int h = 0; h < 2; ++h)
#pragma unroll
            for (int k = 0; k < 4; ++k) vr[mi][h][k] = 0.0f;

#pragma unroll
    for (int ni = 0; ni < 4; ++ni) {
        float vc[2][4] = {{0, 0, 0, 0}, {0, 0, 0, 0}};
        int c0 = wn * 32 + ni * 8 + qc;
        int lj0 = sLab[128 + c0];
        int lj1 = sLab[128 + c0 + 1];
#pragma unroll
        for (int mi = 0; mi < 4; ++mi) {
            int r0 = rl0[mi], r1 = r0 + 8;
            contrib2(acc[mi][ni][0], diag && (r0 == c0),     lb0a[mi] == lj0, vr[mi][0], vc[0]);
            contrib2(acc[mi][ni][1], diag && (r0 == c0 + 1), lb0a[mi] == lj1, vr[mi][0], vc[1]);
            contrib2(acc[mi][ni][2], diag && (r1 == c0),     lb1a[mi] == lj0, vr[mi][1], vc[0]);
            contrib2(acc[mi][ni][3], diag && (r1 == c0 + 1), lb1a[mi] == lj1, vr[mi][1], vc[1]);
        }
        if (!diag) {
            // reduce over the 8 qrow lanes (covers all 16 rows per mi, all mi)
#pragma unroll
            for (int e = 0; e < 2; ++e)
#pragma unroll
                for (int k = 0; k < 4; ++k) {
                    vc[e][k] += __shfl_xor_sync(0xffffffffu, vc[e][k], 4);
                    vc[e][k] += __shfl_xor_sync(0xffffffffu, vc[e][k], 8);
                    vc[e][k] += __shfl_xor_sync(0xffffffffu, vc[e][k], 16);
                }
            if (lane < 4) {
#pragma unroll
                for (int e = 0; e < 2; ++e)
#pragma unroll
                    for (int k = 0; k < 4; ++k)
                        atomicAdd(&colAcc[(c0 + e) * 4 + k], vc[e][k]);
            }
        }
    }

#pragma unroll
    for (int mi = 0; mi < 4; ++mi) {
#pragma unroll
        for (int h = 0; h < 2; ++h) {
#pragma unroll
            for (int k = 0; k < 4; ++k) {
                vr[mi][h][k] += __shfl_xor_sync(0xffffffffu, vr[mi][h][k], 1);
                vr[mi][h][k] += __shfl_xor_sync(0xffffffffu, vr[mi][h][k], 2);
            }
            if ((lane & 3) == 0) {
                int r = rl0[mi] + h * 8;
#pragma unroll
                for (int k = 0; k < 4; ++k)
                    atomicAdd(&rowAcc[r * 4 + k], vr[mi][h][k]);
            }
        }
    }
    __syncthreads();

    if (t < 128) {
        int gr = i0 + t;
#pragma unroll
        for (int k = 0; k < 4; ++k)
            atomicAdd(&g_rowstats[k * NB + gr], rowAcc[t * 4 + k]);
    } else if (!diag) {
        int gc = j0 + (t - 128);
#pragma unroll
        for (int k = 0; k < 4; ++k)
            atomicAdd(&g_rowstats[k * NB + gc], colAcc[(t - 128) * 4 + k]);
    }
}

// ------------------------------------------------- kernel 3: finalize to scalar
__global__ void finalize_kernel(const int* __restrict__ labels, float* __restrict__ out) {
    __shared__ int hist[1024];
    __shared__ float sp[256], sn[256];
    int t = threadIdx.x;
    for (int k = t; k < 1024; k += 256) hist[k] = 0;
    __syncthreads();
    for (int r = t; r < NB; r += 256) atomicAdd(&hist[labels[r]], 1);
    __syncthreads();

    float ps = 0.0f, ns = 0.0f;
    for (int r = t; r < NB; r += 256) {
        float denom = g_rowstats[r];
        float S1 = g_rowstats[NB + r];
        float W1 = g_rowstats[2 * NB + r];
        float S2 = g_rowstats[3 * NB + r];
        int pc_actual = hist[labels[r]] - 1;
        float pc = fmaxf((float)pc_actual, 1.0f);
        float nc = fmaxf((float)(NB - 1 - pc_actual), 1.0f);
        float logd = __logf(denom);
        ps -= (S1 - W1 * logd) / pc;
        ns += (S2 / denom) / nc;
    }
    sp[t] = ps; sn[t] = ns;
    __syncthreads();
#pragma unroll
    for (int s = 128; s > 0; s >>= 1) {
        if (t < s) { sp[t] += sp[t + s]; sn[t] += sn[t + s]; }
        __syncthreads();
    }
    if (t == 0) out[0] = sp[0] * (1.0f / NB) + NEG_W * (sn[0] * (1.0f / NB));
}

// ------------------------------------------------- launch
extern "C" void kernel_launch(void* const* d_in, const int* in_sizes, int n_in,
                              void* d_out, int out_size) {
    const float* feat;
    const int* labels;
    if (in_sizes[0] == NB * DD) {
        feat = (const float*)d_in[0];
        labels = (const int*)d_in[1];
    } else {
        feat = (const float*)d_in[1];
        labels = (const int*)d_in[0];
    }

    cudaFuncSetAttribute(w2ml_main_kernel,
                         cudaFuncAttributeMaxDynamicSharedMemorySize, SMEM_BYTES);

    norm_zero_kernel<<<NB / 8, 256>>>(feat);

    w2ml_main_kernel<<<NTILES, 256, SMEM_BYTES>>>(labels);

    finalize_kernel<<<1, 256>>>(labels, (float*)d_out);
}

// round 6
// speedup vs baseline: 1.4803x; 1.0020x over previous
#include <cuda_runtime.h>
#include <cuda_bf16.h>
#include <cstdint>

#define NB 8192
#define DD 256
#define BM 128
#define BN 128
#define BK 64
#define NT 64                           // tiles per dimension (NB/BM)
#define NTILES (NT * (NT + 1) / 2)      // 2080 upper-triangular tiles
#define LDS_ST 72                       // padded bf16 row stride (conflict-free ldmatrix)
#define STAGE_ELEMS (BM * LDS_ST)       // 9216 bf16
#define STAGE_BYTES (STAGE_ELEMS * 2)   // 18432 B
// 4 stages + 256 labels + rowAcc[128][4] + colAcc[128][4]
#define SMEM_BYTES (4 * STAGE_BYTES + 256 * 4 + 2 * BM * 4 * 4)  // 78848 B

#define INV_T 14.285714285714286f
#define NEG_W 0.3f

__device__ __nv_bfloat16 g_nrm[NB * DD];   // normalized features, bf16
__device__ float g_rowstats[4 * NB];       // [denom, S1, W1, S2] x NB

// ---------------------------------------------------------------- helpers
__device__ __forceinline__ void cp_async16(void* dst, const void* src) {
    unsigned s = (unsigned)__cvta_generic_to_shared(dst);
    asm volatile("cp.async.cg.shared.global [%0], [%1], 16;\n" :: "r"(s), "l"(src));
}

__device__ __forceinline__ void ldsm4(uint32_t& r0, uint32_t& r1, uint32_t& r2, uint32_t& r3,
                                      unsigned addr) {
    asm volatile("ldmatrix.sync.aligned.m8n8.x4.shared.b16 {%0,%1,%2,%3}, [%4];\n"
                 : "=r"(r0), "=r"(r1), "=r"(r2), "=r"(r3) : "r"(addr));
}

__device__ __forceinline__ void mma16816(float* d, const uint32_t* a, const uint32_t* b) {
    asm volatile(
        "mma.sync.aligned.m16n8k16.row.col.f32.bf16.bf16.f32 "
        "{%0,%1,%2,%3}, {%4,%5,%6,%7}, {%8,%9}, {%0,%1,%2,%3};\n"
        : "+f"(d[0]), "+f"(d[1]), "+f"(d[2]), "+f"(d[3])
        : "r"(a[0]), "r"(a[1]), "r"(a[2]), "r"(a[3]), "r"(b[0]), "r"(b[1]));
}

__device__ __forceinline__ void prefetch_tiles(const __nv_bfloat16* gA, const __nv_bfloat16* gB,
                                               __nv_bfloat16* sA, __nv_bfloat16* sB, int t) {
#pragma unroll
    for (int it = 0; it < 4; ++it) {
        int c = t + it * 256;
        int r = c >> 3, cc = c & 7;
        cp_async16(sA + r * LDS_ST + cc * 8, gA + (size_t)r * DD + cc * 8);
        cp_async16(sB + r * LDS_ST + cc * 8, gB + (size_t)r * DD + cc * 8);
    }
}

// one symmetric contribution: adds 4-stat vector to a row acc and a col acc
__device__ __forceinline__ void contrib2(float s, bool self, bool same,
                                         float* vr, float* vc) {
    if (self) return;
    float l = (s - 1.0f) * INV_T;
    float e = __expf(l);
    float a1, a2, a3;
    if (same) {
        float w = (s < 0.5f) ? (1.5f - s) : 1.0f;   // 1+(0.5-s)/0.5*0.5 (continuous)
        a1 = w * l; a2 = w; a3 = 0.0f;
    } else {
        float w = (s > 0.3f) ? fmaf(s - 0.3f, 1.4285714285714286f, 1.0f) : 1.0f;
        a1 = 0.0f; a2 = 0.0f; a3 = w * e;
    }
    vr[0] += e;  vr[1] += a1; vr[2] += a2; vr[3] += a3;
    vc[0] += e;  vc[1] += a1; vc[2] += a2; vc[3] += a3;
}

// ------------------------------------------------- kernel 1: normalize + zero stats
__global__ void norm_zero_kernel(const float* __restrict__ feat) {
    int gt = blockIdx.x * 256 + threadIdx.x;
    if (gt < 4 * NB) g_rowstats[gt] = 0.0f;

    int warp = threadIdx.x >> 5;
    int lane = threadIdx.x & 31;
    int row = blockIdx.x * 8 + warp;

    const float4* src = reinterpret_cast<const float4*>(feat) + (size_t)row * (DD / 4) + lane * 2;
    float4 a = src[0];
    float4 b = src[1];
    float ss = a.x * a.x + a.y * a.y + a.z * a.z + a.w * a.w
             + b.x * b.x + b.y * b.y + b.z * b.z + b.w * b.w;
#pragma unroll
    for (int o = 16; o > 0; o >>= 1) ss += __shfl_xor_sync(0xffffffffu, ss, o);
    float inv = rsqrtf(ss);

    union { __nv_bfloat162 h[4]; uint4 u; } pk;
    pk.h[0] = __floats2bfloat162_rn(a.x * inv, a.y * inv);
    pk.h[1] = __floats2bfloat162_rn(a.z * inv, a.w * inv);
    pk.h[2] = __floats2bfloat162_rn(b.x * inv, b.y * inv);
    pk.h[3] = __floats2bfloat162_rn(b.z * inv, b.w * inv);
    reinterpret_cast<uint4*>(g_nrm)[(size_t)row * (DD / 8) + lane] = pk.u;
}

// ------------------------------------------------- kernel 2: fused GEMM + W2ML epilogue
// One CTA per upper-triangular tile (bi <= bj). Off-diagonal tiles produce row
// stats for BOTH the row block (reduce over j) and the column block (reduce
// over i) from one GEMM, exploiting sim symmetry.
__global__ __launch_bounds__(256, 2)
void w2ml_main_kernel(const int* __restrict__ labels) {
    extern __shared__ char smem[];
    __nv_bfloat16* As = reinterpret_cast<__nv_bfloat16*>(smem);      // [2][128][72]
    __nv_bfloat16* Bs = As + 2 * STAGE_ELEMS;                        // [2][128][72]
    int* sLab = reinterpret_cast<int*>(Bs + 2 * STAGE_ELEMS);        // [256]
    float* rowAcc = reinterpret_cast<float*>(sLab + 256);            // [128][4]
    float* colAcc = rowAcc + BM * 4;                                 // [128][4]

    const int t = threadIdx.x;

    // decode linear tile id -> (bi, bj), bi <= bj
    int id = blockIdx.x;
    int bi = (int)((2.0f * NT + 1.0f -
                    sqrtf((2.0f * NT + 1.0f) * (2.0f * NT + 1.0f) - 8.0f * (float)id)) * 0.5f);
    // fixups (start(b) = b*(2*NT - b + 1)/2)
    while ((bi + 1) * (2 * NT - bi) / 2 <= id) ++bi;
    while (bi * (2 * NT - bi + 1) / 2 > id) --bi;
    const int bj = bi + (id - bi * (2 * NT - bi + 1) / 2);
    const bool diag = (bi == bj);

    const int i0 = bi * BM;
    const int j0 = bj * BN;

    if (t < 128) sLab[t] = labels[i0 + t];
    else         sLab[t] = labels[j0 + t - 128];
    for (int k = t; k < 2 * BM * 4; k += 256) rowAcc[k] = 0.0f;

    const int lane = t & 31;
    const int warpId = t >> 5;
    const int wm = warpId >> 2;     // 0..1 (m)
    const int wn = warpId & 3;      // 0..3 (n)

    unsigned aAddr[4], bAddr[2];
    {
        int coff = (lane >> 4) * 8;
#pragma unroll
        for (int mi = 0; mi < 4; ++mi) {
            int r = wm * 64 + mi * 16 + (lane & 15);
            aAddr[mi] = (unsigned)__cvta_generic_to_shared(As + r * LDS_ST + coff);
        }
        int bcoff = ((lane >> 3) & 1) * 8;
#pragma unroll
        for (int np = 0; np < 2; ++np) {
            int r = wn * 32 + np * 16 + (lane & 7) + ((lane >> 4) << 3);
            bAddr[np] = (unsigned)__cvta_generic_to_shared(Bs + r * LDS_ST + bcoff);
        }
    }

    float acc[4][4][4];
#pragma unroll
    for (int mi = 0; mi < 4; ++mi)
#pragma unroll
        for (int ni = 0; ni < 4; ++ni)
#pragma unroll
            for (int r = 0; r < 4; ++r) acc[mi][ni][r] = 0.0f;

    const __nv_bfloat16* gA = g_nrm + (size_t)i0 * DD;
    const __nv_bfloat16* gB = g_nrm + (size_t)j0 * DD;

    prefetch_tiles(gA, gB, As, Bs, t);
    asm volatile("cp.async.commit_group;\n" ::: "memory");

#pragma unroll
    for (int kb = 0; kb < 4; ++kb) {
        if (kb < 3) {
            int st = (kb + 1) & 1;
            prefetch_tiles(gA + (kb + 1) * BK, gB + (kb + 1) * BK,
                           As + st * STAGE_ELEMS, Bs + st * STAGE_ELEMS, t);
            asm volatile("cp.async.commit_group;\n" ::: "memory");
            asm volatile("cp.async.wait_group 1;\n" ::: "memory");
        } else {
            asm volatile("cp.async.wait_group 0;\n" ::: "memory");
        }
        __syncthreads();

        unsigned soff = (kb & 1) * STAGE_BYTES;
#pragma unroll
        for (int ks = 0; ks < 4; ++ks) {
            unsigned off = soff + ks * 32;
            uint32_t bf[4][2];
#pragma unroll
            for (int np = 0; np < 2; ++np) {
                uint32_t r0, r1, r2, r3;
                ldsm4(r0, r1, r2, r3, bAddr[np] + off);
                bf[np * 2][0] = r0;     bf[np * 2][1] = r1;
                bf[np * 2 + 1][0] = r2; bf[np * 2 + 1][1] = r3;
            }
#pragma unroll
            for (int mi = 0; mi < 4; ++mi) {
                uint32_t a[4];
                ldsm4(a[0], a[1], a[2], a[3], aAddr[mi] + off);
#pragma unroll
                for (int ni = 0; ni < 4; ++ni) mma16816(acc[mi][ni], a, bf[ni]);
            }
        }
        __syncthreads();
    }

    // ---- epilogue: symmetric W2ML terms -> row stats + column(=transposed row) stats
    const int qrow = lane >> 2;
    const int qc = (lane & 3) << 1;

    int lb0a[4], lb1a[4], rl0[4];
#pragma unroll
    for (int mi = 0; mi < 4; ++mi) {
        int r0 = wm * 64 + mi * 16 + qrow;
        rl0[mi] = r0;
        lb0a[mi] = sLab[r0];
        lb1a[mi] = sLab[r0 + 8];
    }

    float vr[4][2][4];
#pragma unroll
    for (int mi = 0; mi < 4; ++mi)
#pragma unroll
        for (int h = 0; h < 2; ++h)
#pragma unroll
            for (int k = 0; k < 4; ++k) vr[mi][h][k] = 0.0f;

#pragma unroll
    for (int ni = 0; ni < 4; ++ni) {
        float vc[2][4] = {{0, 0, 0, 0}, {0, 0, 0, 0}};
        int c0 = wn * 32 + ni * 8 + qc;
        int lj0 = sLab[128 + c0];
        int lj1 = sLab[128 + c0 + 1];
#pragma unroll
        for (int mi = 0; mi < 4; ++mi) {
            int r0 = rl0[mi], r1 = r0 + 8;
            contrib2(acc[mi][ni][0], diag && (r0 == c0),     lb0a[mi] == lj0, vr[mi][0], vc[0]);
            contrib2(acc[mi][ni][1], diag && (r0 == c0 + 1), lb0a[mi] == lj1, vr[mi][0], vc[1]);
            contrib2(acc[mi][ni][2], diag && (r1 == c0),     lb1a[mi] == lj0, vr[mi][1], vc[0]);
            contrib2(acc[mi][ni][3], diag && (r1 == c0 + 1), lb1a[mi] == lj1, vr[mi][1], vc[1]);
        }
        if (!diag) {
            // reduce over the 8 qrow lanes (covers all 16 rows per mi, all mi)
#pragma unroll
            for (int e = 0; e < 2; ++e)
#pragma unroll
                for (int k = 0; k < 4; ++k) {
                    vc[e][k] += __shfl_xor_sync(0xffffffffu, vc[e][k], 4);
                    vc[e][k] += __shfl_xor_sync(0xffffffffu, vc[e][k], 8);
                    vc[e][k] += __shfl_xor_sync(0xffffffffu, vc[e][k], 16);
                }
            if (lane < 4) {
#pragma unroll
                for (int e = 0; e < 2; ++e)
#pragma unroll
                    for (int k = 0; k < 4; ++k)
                        atomicAdd(&colAcc[(c0 + e) * 4 + k], vc[e][k]);
            }
        }
    }

#pragma unroll
    for (int mi = 0; mi < 4; ++mi) {
#pragma unroll
        for (int h = 0; h < 2; ++h) {
#pragma unroll
            for (int k = 0; k < 4; ++k) {
                vr[mi][h][k] += __shfl_xor_sync(0xffffffffu, vr[mi][h][k], 1);
                vr[mi][h][k] += __shfl_xor_sync(0xffffffffu, vr[mi][h][k], 2);
            }
            if ((lane & 3) == 0) {
                int r = rl0[mi] + h * 8;
#pragma unroll
                for (int k = 0; k < 4; ++k)
                    atomicAdd(&rowAcc[r * 4 + k], vr[mi][h][k]);
            }
        }
    }
    __syncthreads();

    if (t < 128) {
        int gr = i0 + t;
#pragma unroll
        for (int k = 0; k < 4; ++k)
            atomicAdd(&g_rowstats[k * NB + gr], rowAcc[t * 4 + k]);
    } else if (!diag) {
        int gc = j0 + (t - 128);
#pragma unroll
        for (int k = 0; k < 4; ++k)
            atomicAdd(&g_rowstats[k * NB + gc], colAcc[(t - 128) * 4 + k]);
    }
}

// ------------------------------------------------- kernel 3: finalize to scalar
__global__ void finalize_kernel(const int* __restrict__ labels, float* __restrict__ out) {
    __shared__ int hist[1024];
    __shared__ float sp[256], sn[256];
    int t = threadIdx.x;
    for (int k = t; k < 1024; k += 256) hist[k] = 0;
    __syncthreads();
    for (int r = t; r < NB; r += 256) atomicAdd(&hist[labels[r]], 1);
    __syncthreads();

    float ps = 0.0f, ns = 0.0f;
    for (int r = t; r < NB; r += 256) {
        float denom = g_rowstats[r];
        float S1 = g_rowstats[NB + r];
        float W1 = g_rowstats[2 * NB + r];
        float S2 = g_rowstats[3 * NB + r];
        int pc_actual = hist[labels[r]] - 1;
        float pc = fmaxf((float)pc_actual, 1.0f);
        float nc = fmaxf((float)(NB - 1 - pc_actual), 1.0f);
        float logd = __logf(denom);
        ps -= (S1 - W1 * logd) / pc;
        ns += (S2 / denom) / nc;
    }
    sp[t] = ps; sn[t] = ns;
    __syncthreads();
#pragma unroll
    for (int s = 128; s > 0; s >>= 1) {
        if (t < s) { sp[t] += sp[t + s]; sn[t] += sn[t + s]; }
        __syncthreads();
    }
    if (t == 0) out[0] = sp[0] * (1.0f / NB) + NEG_W * (sn[0] * (1.0f / NB));
}

// ------------------------------------------------- launch
extern "C" void kernel_launch(void* const* d_in, const int* in_sizes, int n_in,
                              void* d_out, int out_size) {
    const float* feat;
    const int* labels;
    if (in_sizes[0] == NB * DD) {
        feat = (const float*)d_in[0];
        labels = (const int*)d_in[1];
    } else {
        feat = (const float*)d_in[1];
        labels = (const int*)d_in[0];
    }

    cudaFuncSetAttribute(w2ml_main_kernel,
                         cudaFuncAttributeMaxDynamicSharedMemorySize, SMEM_BYTES);

    norm_zero_kernel<<<NB / 8, 256>>>(feat);

    w2ml_main_kernel<<<NTILES, 256, SMEM_BYTES>>>(labels);

    finalize_kernel<<<1, 256>>>(labels, (float*)d_out);
}